// round 1
// baseline (speedup 1.0000x reference)
#include <cuda_runtime.h>
#include <math.h>

#define N_NODES 50000
#define F_IN    1433
#define HDIM    256
#define NCLS    7

// ---------------- scratch (static device allocations; no cudaMalloc) ----------------
__device__ float g_deg[N_NODES];
__device__ float g_dinv[N_NODES];
__device__ float g_h[N_NODES * HDIM];     // GEMM output (pre-aggregation)
__device__ float g_a[N_NODES * HDIM];     // aggregation output (next layer input)
__device__ float g_h3[N_NODES * 8];       // layer-3 GEMM output (padded stride 8)
__device__ float g_a3[N_NODES * 8];       // layer-3 aggregation output

// ---------------- degree / normalization ----------------
__global__ void k_deg_init() {
    int i = blockIdx.x * blockDim.x + threadIdx.x;
    if (i < N_NODES) g_deg[i] = 1.0f;  // self-loop contribution
}

__global__ void k_deg_edges(const int* __restrict__ dst, int E) {
    int e = blockIdx.x * blockDim.x + threadIdx.x;
    if (e < E) atomicAdd(&g_deg[dst[e]], 1.0f);
}

__global__ void k_dinv() {
    int i = blockIdx.x * blockDim.x + threadIdx.x;
    if (i < N_NODES) g_dinv[i] = rsqrtf(g_deg[i]);  // deg >= 1 always
}

// ---------------- tiled fp32 GEMM: C[M,Nf] = op(A)[M,K] @ B[K,Nf] ----------------
// BM=128, BN=64, BK=16, 256 threads, each thread computes 8x4.
// RELU applies relu to A elements on load (fused activation of previous layer).
template<bool RELU>
__global__ __launch_bounds__(256)
void k_gemm(const float* __restrict__ A, const float* __restrict__ B,
            float* __restrict__ Cmat, int M, int K, int Nf) {
    const int BM = 128, BN = 64, BK = 16, TM = 8, TN = 4;
    __shared__ float As[BK][BM + 4];   // +4 pad: avoids full-bank write conflicts
    __shared__ float Bs[BK][BN];

    int tid = threadIdx.x;
    int nx  = tid & 15;   // 0..15 -> n sub-tile
    int my  = tid >> 4;   // 0..15 -> m sub-tile
    int m0  = blockIdx.x * BM;
    int n0  = blockIdx.y * BN;

    float acc[TM][TN];
#pragma unroll
    for (int i = 0; i < TM; i++)
#pragma unroll
        for (int j = 0; j < TN; j++) acc[i][j] = 0.0f;

    for (int k0 = 0; k0 < K; k0 += BK) {
        // load A tile (128x16) transposed into As[k][m]
#pragma unroll
        for (int r = 0; r < 8; r++) {
            int idx = r * 256 + tid;
            int am = idx >> 4, ak = idx & 15;
            int gm = m0 + am, gk = k0 + ak;
            float v = 0.0f;
            if (gm < M && gk < K) v = A[(long)gm * K + gk];
            if (RELU) v = fmaxf(v, 0.0f);
            As[ak][am] = v;
        }
        // load B tile (16x64)
#pragma unroll
        for (int r = 0; r < 4; r++) {
            int idx = r * 256 + tid;
            int bk = idx >> 6, bn = idx & 63;
            int gk = k0 + bk;
            Bs[bk][bn] = (gk < K) ? B[(long)gk * Nf + n0 + bn] : 0.0f;
        }
        __syncthreads();

#pragma unroll
        for (int k = 0; k < BK; k++) {
            float a[TM], b[TN];
#pragma unroll
            for (int i = 0; i < TM; i++) a[i] = As[k][my * TM + i];
#pragma unroll
            for (int j = 0; j < TN; j++) b[j] = Bs[k][nx * TN + j];
#pragma unroll
            for (int i = 0; i < TM; i++)
#pragma unroll
                for (int j = 0; j < TN; j++)
                    acc[i][j] = fmaf(a[i], b[j], acc[i][j]);
        }
        __syncthreads();
    }

    // store (float4 per row of the micro-tile)
#pragma unroll
    for (int i = 0; i < TM; i++) {
        int gm = m0 + my * TM + i;
        if (gm < M) {
            float4 v = make_float4(acc[i][0], acc[i][1], acc[i][2], acc[i][3]);
            *reinterpret_cast<float4*>(&Cmat[(long)gm * Nf + n0 + nx * TN]) = v;
        }
    }
}

// ---------------- aggregation (H=256): out = bias + self-loop, then edge scatter ----------------
__global__ void k_agg_init(const float* __restrict__ h, const float* __restrict__ bias,
                           float* __restrict__ out) {
    // one thread per float4: N*64 threads
    int idx = blockIdx.x * blockDim.x + threadIdx.x;
    int node = idx >> 6;
    int f4   = idx & 63;
    if (node >= N_NODES) return;
    float d = g_dinv[node];
    float s = d * d;
    float4 hv = reinterpret_cast<const float4*>(h)[node * 64 + f4];
    float4 bv = reinterpret_cast<const float4*>(bias)[f4];
    float4 o;
    o.x = bv.x + hv.x * s;
    o.y = bv.y + hv.y * s;
    o.z = bv.z + hv.z * s;
    o.w = bv.w + hv.w * s;
    reinterpret_cast<float4*>(out)[node * 64 + f4] = o;
}

__global__ void k_agg_edges(const float* __restrict__ h,
                            const int* __restrict__ src, const int* __restrict__ dst,
                            float* __restrict__ out, int E) {
    // 64 threads per edge, each handles one float4 (4 scalar atomics)
    int t = blockIdx.x * blockDim.x + threadIdx.x;
    int e  = t >> 6;
    int f4 = t & 63;
    if (e >= E) return;
    int r = __ldg(&src[e]);
    int c = __ldg(&dst[e]);
    float nrm = g_dinv[r] * g_dinv[c];
    float4 hv = reinterpret_cast<const float4*>(h + (long)r * HDIM)[f4];
    float* o = out + (long)c * HDIM + f4 * 4;
    atomicAdd(o + 0, hv.x * nrm);
    atomicAdd(o + 1, hv.y * nrm);
    atomicAdd(o + 2, hv.z * nrm);
    atomicAdd(o + 3, hv.w * nrm);
}

// ---------------- layer 3: warp-per-row GEMM [N,256] x [256,7] with fused relu ----------------
__global__ __launch_bounds__(256)
void k_gemm3(const float* __restrict__ A, const float* __restrict__ W) {
    __shared__ float Ws[256 * NCLS];
    int tid = threadIdx.x;
    for (int i = tid; i < 256 * NCLS; i += 256) Ws[i] = W[i];
    __syncthreads();

    int warp = tid >> 5, lane = tid & 31;
    int row = blockIdx.x * 8 + warp;
    if (row >= N_NODES) return;

    float acc[NCLS];
#pragma unroll
    for (int c = 0; c < NCLS; c++) acc[c] = 0.0f;

    const float* a = A + (long)row * HDIM;
    for (int k = lane; k < HDIM; k += 32) {
        float v = fmaxf(a[k], 0.0f);
#pragma unroll
        for (int c = 0; c < NCLS; c++) acc[c] = fmaf(v, Ws[k * NCLS + c], acc[c]);
    }
#pragma unroll
    for (int c = 0; c < NCLS; c++) {
#pragma unroll
        for (int off = 16; off; off >>= 1)
            acc[c] += __shfl_down_sync(0xffffffffu, acc[c], off);
    }
    if (lane == 0) {
#pragma unroll
        for (int c = 0; c < NCLS; c++) g_h3[row * 8 + c] = acc[c];
    }
}

__global__ void k_agg3_init(const float* __restrict__ b3) {
    int t = blockIdx.x * blockDim.x + threadIdx.x;
    int node = t >> 3;
    int c    = t & 7;
    if (node >= N_NODES || c >= NCLS) return;
    float d = g_dinv[node];
    g_a3[node * 8 + c] = b3[c] + g_h3[node * 8 + c] * d * d;
}

__global__ void k_agg3_edges(const int* __restrict__ src, const int* __restrict__ dst, int E) {
    int t = blockIdx.x * blockDim.x + threadIdx.x;
    int e = t >> 3;
    int c = t & 7;
    if (e >= E || c >= NCLS) return;
    int r = __ldg(&src[e]);
    int d = __ldg(&dst[e]);
    float nrm = g_dinv[r] * g_dinv[d];
    atomicAdd(&g_a3[d * 8 + c], g_h3[r * 8 + c] * nrm);
}

__global__ void k_log_softmax(float* __restrict__ out) {
    int i = blockIdx.x * blockDim.x + threadIdx.x;
    if (i >= N_NODES) return;
    float v[NCLS];
    float m = -INFINITY;
#pragma unroll
    for (int c = 0; c < NCLS; c++) { v[c] = g_a3[i * 8 + c]; m = fmaxf(m, v[c]); }
    float s = 0.0f;
#pragma unroll
    for (int c = 0; c < NCLS; c++) s += __expf(v[c] - m);
    float lse = m + __logf(s);
    // use accurate exp/log? fast intrinsics give ~1e-6 rel err on these magnitudes; fine vs 1e-3
#pragma unroll
    for (int c = 0; c < NCLS; c++) out[i * NCLS + c] = v[c] - lse;
}

// ---------------- launch ----------------
extern "C" void kernel_launch(void* const* d_in, const int* in_sizes, int n_in,
                              void* d_out, int out_size) {
    const float* x  = (const float*)d_in[0];
    const int*   ei = (const int*)d_in[1];
    const float* W1 = (const float*)d_in[2];
    const float* b1 = (const float*)d_in[3];
    const float* W2 = (const float*)d_in[4];
    const float* b2 = (const float*)d_in[5];
    const float* W3 = (const float*)d_in[6];
    const float* b3 = (const float*)d_in[7];
    float* out = (float*)d_out;

    const int E = in_sizes[1] / 2;
    const int* src = ei;       // edge_index[0]
    const int* dst = ei + E;   // edge_index[1]

    float *gh, *ga, *gh3_unused;
    (void)gh3_unused;
    cudaGetSymbolAddress((void**)&gh, g_h);
    cudaGetSymbolAddress((void**)&ga, g_a);

    // 1) normalization coefficients
    k_deg_init<<<(N_NODES + 255) / 256, 256>>>();
    k_deg_edges<<<(E + 255) / 256, 256>>>(dst, E);
    k_dinv<<<(N_NODES + 255) / 256, 256>>>();

    dim3 gemm_grid((N_NODES + 127) / 128, HDIM / 64);

    // 2) layer 1: h = x @ W1 ; agg ; (+b1, relu fused into next gemm load)
    k_gemm<false><<<gemm_grid, 256>>>(x, W1, gh, N_NODES, F_IN, HDIM);
    {
        long t = (long)N_NODES * 64;
        k_agg_init<<<(unsigned)((t + 255) / 256), 256>>>(gh, b1, ga);
        long te = (long)E * 64;
        k_agg_edges<<<(unsigned)((te + 255) / 256), 256>>>(gh, src, dst, ga, E);
    }

    // 3) layer 2: h = relu(a) @ W2 ; agg
    k_gemm<true><<<gemm_grid, 256>>>(ga, W2, gh, N_NODES, HDIM, HDIM);
    {
        long t = (long)N_NODES * 64;
        k_agg_init<<<(unsigned)((t + 255) / 256), 256>>>(gh, b2, ga);
        long te = (long)E * 64;
        k_agg_edges<<<(unsigned)((te + 255) / 256), 256>>>(gh, src, dst, ga, E);
    }

    // 4) layer 3: h3 = relu(a) @ W3 ; agg ; log_softmax
    k_gemm3<<<(N_NODES + 7) / 8, 256>>>(ga, W3);
    {
        long t = (long)N_NODES * 8;
        k_agg3_init<<<(unsigned)((t + 255) / 256), 256>>>(b3);
        long te = (long)E * 8;
        k_agg3_edges<<<(unsigned)((te + 255) / 256), 256>>>(src, dst, E);
    }
    k_log_softmax<<<(N_NODES + 255) / 256, 256>>>(out);
}